// round 16
// baseline (speedup 1.0000x reference)
#include <cuda_runtime.h>
#include <cuda_bf16.h>
#include <cstdint>
#include <math.h>

#define NPIX 65536  // 256*256

// ---------------- scratch (device globals; no allocation allowed) -------------
__device__ float g_vp[33554432];   // vp_pc: [b][p][256] f32 (token-major)
__device__ float g_qk[16777216];   // qk_pc: [b][p][128] f32 (qp | kp)
__device__ float g_attn[33554432]; // planar [b][c][p]
__device__ float g_dw[33554432];   // planar
__device__ float g_biasT[32768];   // [h][m][r]
__device__ __nv_bfloat16 g_Th[33554432];  // transposed hi  [b][p][c]  (v / dw)
__device__ __nv_bfloat16 g_Tl[33554432];  // transposed lo
__device__ __nv_bfloat16 g_qTh[8388608], g_qTl[8388608];  // q transposed [b][p][64]
__device__ __nv_bfloat16 g_Wsh[8192], g_Wsl[8192];        // [Wq*s;Wkq] 128x64
__device__ __nv_bfloat16 g_Wvh[65536], g_Wvl[65536];
__device__ __nv_bfloat16 g_pwh[65536], g_pwl[65536];

// ================= helpers ======================================================
__device__ __forceinline__ uint32_t smem_u32(const void* p) {
    uint32_t a;
    asm("{ .reg .u64 t; cvta.to.shared.u64 t, %1; cvt.u32.u64 %0, t; }" : "=r"(a) : "l"(p));
    return a;
}
__device__ __forceinline__ void ldsm4(uint32_t* r, uint32_t addr) {
    asm volatile("ldmatrix.sync.aligned.m8n8.x4.shared.b16 {%0,%1,%2,%3}, [%4];"
                 : "=r"(r[0]), "=r"(r[1]), "=r"(r[2]), "=r"(r[3]) : "r"(addr));
}
__device__ __forceinline__ void mma16816(float* c, const uint32_t* a, const uint32_t* b) {
    asm volatile(
        "mma.sync.aligned.m16n8k16.row.col.f32.bf16.bf16.f32 "
        "{%0,%1,%2,%3}, {%4,%5,%6,%7}, {%8,%9}, {%0,%1,%2,%3};"
        : "+f"(c[0]), "+f"(c[1]), "+f"(c[2]), "+f"(c[3])
        : "r"(a[0]), "r"(a[1]), "r"(a[2]), "r"(a[3]), "r"(b[0]), "r"(b[1]));
}
__device__ __forceinline__ void cp16(uint32_t saddr, const void* g) {
    asm volatile("cp.async.cg.shared.global [%0], [%1], 16;" ::"r"(saddr), "l"(g));
}
#define CP_COMMIT() asm volatile("cp.async.commit_group;" ::: "memory")
#define CP_WAIT0() asm volatile("cp.async.wait_group 0;" ::: "memory")
#define FMA2(d, a, b) asm("fma.rn.f32x2 %0, %1, %2, %0;" : "+l"(d) : "l"(a), "l"(b))
#define MUL2(d, a, b) asm("mul.rn.f32x2 %0, %1, %2;" : "=l"(d) : "l"(a), "l"(b))
#define PACK2(d, lo, hi) asm("mov.b64 %0, {%1, %2};" : "=l"(d) : "f"(lo), "f"(hi))
#define UNPACK2(lo, hi, d) asm("mov.b64 {%0, %1}, %2;" : "=f"(lo), "=f"(hi) : "l"(d))

// ---------------- transpose + hi/lo convert body --------------------------------
template <int CDIM>
__device__ __forceinline__ void convT_body(const float* __restrict__ X,
                                           __nv_bfloat16* __restrict__ Th,
                                           __nv_bfloat16* __restrict__ Tl,
                                           int p0, int c0, int b) {
    __shared__ float s[64][65];
    const int tid = threadIdx.x;
    const float* Xb = X + ((size_t)b * CDIM + c0) * NPIX + p0;
#pragma unroll
    for (int i = 0; i < 16; i++) {
        int idx = tid + i * 256;
        int c = idx >> 6, p = idx & 63;
        s[c][p] = Xb[(size_t)c * NPIX + p];
    }
    __syncthreads();
    const size_t ob = ((size_t)b * NPIX + p0) * CDIM + c0;
#pragma unroll
    for (int i = 0; i < 16; i++) {
        int idx = tid + i * 256;
        int p = idx >> 6, c = idx & 63;
        float x = s[c][p];
        __nv_bfloat16 h = __float2bfloat16(x);
        Th[ob + (size_t)p * CDIM + c] = h;
        Tl[ob + (size_t)p * CDIM + c] = __float2bfloat16(x - __bfloat162float(h));
    }
}

// merged: y==0 -> q transpose, y in 1..4 -> v transpose, y==5 -> prep (z==0 only)
__global__ __launch_bounds__(256) void convT_all(
    const float* __restrict__ q, const float* __restrict__ v,
    __nv_bfloat16* __restrict__ qth, __nv_bfloat16* __restrict__ qtl,
    __nv_bfloat16* __restrict__ th, __nv_bfloat16* __restrict__ tl,
    const float* __restrict__ Wk, const float* __restrict__ Wq,
    const float* __restrict__ bias_table, const int* __restrict__ rel,
    const float* __restrict__ Wv, const float* __restrict__ pw,
    __nv_bfloat16* __restrict__ Wsh, __nv_bfloat16* __restrict__ Wsl,
    float* __restrict__ biasT,
    __nv_bfloat16* __restrict__ Wvh, __nv_bfloat16* __restrict__ Wvl,
    __nv_bfloat16* __restrict__ pwh, __nv_bfloat16* __restrict__ pwl) {
    if (blockIdx.y == 0) {
        convT_body<64>(q, qth, qtl, blockIdx.x * 64, 0, blockIdx.z);
    } else if (blockIdx.y <= 4) {
        convT_body<256>(v, th, tl, blockIdx.x * 64, (blockIdx.y - 1) * 64, blockIdx.z);
    } else {
        if (blockIdx.z != 0) return;
        const int bx = blockIdx.x;
        if (bx == 0) {
            __shared__ float swkq[4096];
            const float scale = 0.35355339059327373f;
            for (int idx = threadIdx.x; idx < 4096; idx += 256) {
                int o = idx >> 6, c = idx & 63;
                float s = 0.f;
#pragma unroll 8
                for (int j = 0; j < 64; j++) s += Wk[o * 64 + j] * Wq[j * 64 + c];
                swkq[idx] = s;
                float a = Wq[idx] * scale;
                __nv_bfloat16 h = __float2bfloat16(a);
                Wsh[idx] = h;
                Wsl[idx] = __float2bfloat16(a - __bfloat162float(h));
            }
            __syncthreads();
            for (int idx = threadIdx.x; idx < 4096; idx += 256) {
                float a = swkq[idx];
                __nv_bfloat16 h = __float2bfloat16(a);
                Wsh[4096 + idx] = h;
                Wsl[4096 + idx] = __float2bfloat16(a - __bfloat162float(h));
            }
        } else if (bx <= 128) {
            int idx = (bx - 1) * 256 + threadIdx.x;  // 32768
            int h = idx >> 12, rm = idx & 4095, m = rm >> 6, r = rm & 63;
            biasT[idx] = bias_table[rel[r * 64 + m] * 8 + h];
        } else if (bx <= 384) {
            int idx = (bx - 129) * 256 + threadIdx.x;  // 65536
            float a = Wv[idx];
            __nv_bfloat16 ah = __float2bfloat16(a);
            Wvh[idx] = ah;
            Wvl[idx] = __float2bfloat16(a - __bfloat162float(ah));
            float b = pw[idx];
            __nv_bfloat16 bh = __float2bfloat16(b);
            pwh[idx] = bh;
            pwl[idx] = __float2bfloat16(b - __bfloat162float(bh));
        }
    }
}

// stand-alone for the dw -> pw transpose
__global__ __launch_bounds__(256) void convT256(const float* __restrict__ X,
                                                __nv_bfloat16* __restrict__ Th,
                                                __nv_bfloat16* __restrict__ Tl) {
    convT_body<256>(X, Th, Tl, blockIdx.x * 64, blockIdx.y * 64, blockIdx.z);
}

// ================= HMMA bf16x3 GEMM body (128o x 64p, 3 CTA/SM) =================
#define RS 72
#define SA_H 0
#define SA_L (128 * RS * 2)
#define SB_H (2 * 128 * RS * 2)
#define SB_L (2 * 128 * RS * 2 + 64 * RS * 2)
#define HM_SMEM (2 * 128 * RS * 2 + 2 * 64 * RS * 2)  // 55296 B

template <int CIN, int PCOUT, int CD>
__device__ __forceinline__ void hmma_body(
    const __nv_bfloat16* __restrict__ Wh, const __nv_bfloat16* __restrict__ Wl,
    const __nv_bfloat16* __restrict__ Xh, const __nv_bfloat16* __restrict__ Xl,
    float* __restrict__ Y, int pBase, int oBase, int b, char* smem) {
    const uint32_t sb = smem_u32(smem);
    const int tid = threadIdx.x;
    const int wid = tid >> 5, lane = tid & 31;
    const int wm = wid & 3, wn = wid >> 2;
    const size_t xrow = (size_t)b * NPIX + pBase;
    const int NKC = CIN / 64;

    float acc[2][4][4];
#pragma unroll
    for (int i = 0; i < 2; i++)
#pragma unroll
        for (int j = 0; j < 4; j++)
#pragma unroll
            for (int k = 0; k < 4; k++) acc[i][j][k] = 0.f;

    const int lrow = lane & 15;
    const int lkoff = (lane >> 4) * 8;
    const int arow = tid >> 3, ac8 = tid & 7;

    for (int kc = 0; kc < NKC; kc++) {
        const size_t kb = (size_t)kc * 64;
#pragma unroll
        for (int i = 0; i < 4; i++) {
            int row = arow + i * 32;
            size_t g = (size_t)(oBase + row) * CIN + kb + ac8 * 8;
            uint32_t so = row * (RS * 2) + ac8 * 16;
            cp16(sb + SA_H + so, Wh + g);
            cp16(sb + SA_L + so, Wl + g);
        }
#pragma unroll
        for (int i = 0; i < 2; i++) {
            int row = arow + i * 32;
            size_t g = (xrow + row) * CIN + kb + ac8 * 8;
            uint32_t so = row * (RS * 2) + ac8 * 16;
            cp16(sb + SB_H + so, Xh + g);
            cp16(sb + SB_L + so, Xl + g);
        }
        CP_COMMIT();
        CP_WAIT0();
        __syncthreads();

#pragma unroll
        for (int ks = 0; ks < 4; ks++) {
            const int kbo = ks * 16 + lkoff;
            uint32_t ah[2][4], al[2][4];
#pragma unroll
            for (int mt = 0; mt < 2; mt++) {
                uint32_t ro = (wm * 32 + mt * 16 + lrow) * (RS * 2) + kbo * 2;
                ldsm4(ah[mt], sb + SA_H + ro);
                ldsm4(al[mt], sb + SA_L + ro);
            }
            uint32_t bh[2][4], bl[2][4];
#pragma unroll
            for (int nt = 0; nt < 2; nt++) {
                uint32_t ro = (wn * 32 + nt * 16 + lrow) * (RS * 2) + kbo * 2;
                ldsm4(bh[nt], sb + SB_H + ro);
                ldsm4(bl[nt], sb + SB_L + ro);
            }
#pragma unroll
            for (int mt = 0; mt < 2; mt++) {
#pragma unroll
                for (int n8 = 0; n8 < 4; n8++) {
                    const int nt = n8 >> 1, half = n8 & 1;
                    uint32_t bfh[2] = {bh[nt][half], bh[nt][half + 2]};
                    uint32_t bfl[2] = {bl[nt][half], bl[nt][half + 2]};
                    mma16816(acc[mt][n8], ah[mt], bfh);
                    mma16816(acc[mt][n8], ah[mt], bfl);
                    mma16816(acc[mt][n8], al[mt], bfh);
                }
            }
        }
        __syncthreads();
    }

    if constexpr (PCOUT) {
        float* sO = (float*)smem;
#pragma unroll
        for (int mt = 0; mt < 2; mt++) {
#pragma unroll
            for (int n8 = 0; n8 < 4; n8++) {
                int ml = wm * 32 + mt * 16 + (lane >> 2);
                int pl = wn * 32 + n8 * 8 + (lane & 3) * 2;
                sO[pl * 132 + ml] = acc[mt][n8][0];
                sO[(pl + 1) * 132 + ml] = acc[mt][n8][1];
                sO[pl * 132 + ml + 8] = acc[mt][n8][2];
                sO[(pl + 1) * 132 + ml + 8] = acc[mt][n8][3];
            }
        }
        __syncthreads();
#pragma unroll
        for (int i = 0; i < 8; i++) {
            int idx = tid + i * 256;  // 2048 float4
            int p = idx >> 5, o4 = (idx & 31) * 4;
            *(float4*)(Y + (xrow + p) * CD + oBase + o4) = *(const float4*)(sO + p * 132 + o4);
        }
    } else {
        const int mrow = oBase + wm * 32 + (lane >> 2);
        const int pcol = pBase + wn * 32 + (lane & 3) * 2;
#pragma unroll
        for (int mt = 0; mt < 2; mt++) {
#pragma unroll
            for (int n8 = 0; n8 < 4; n8++) {
                size_t base = ((size_t)(b * 256 + mrow + mt * 16)) * NPIX + pcol + n8 * 8;
                *(float2*)(Y + base) = make_float2(acc[mt][n8][0], acc[mt][n8][1]);
                *(float2*)(Y + base + 8ull * NPIX) = make_float2(acc[mt][n8][2], acc[mt][n8][3]);
            }
        }
    }
}

// merged vp + qk GEMM: y<2 -> vp tile TOKEN-MAJOR (oBase=y*128), y==2 -> qk
__global__ __launch_bounds__(256, 3) void gemm_all(
    const __nv_bfloat16* __restrict__ wvh, const __nv_bfloat16* __restrict__ wvl,
    const __nv_bfloat16* __restrict__ th, const __nv_bfloat16* __restrict__ tl,
    float* __restrict__ vp,
    const __nv_bfloat16* __restrict__ wsh, const __nv_bfloat16* __restrict__ wsl,
    const __nv_bfloat16* __restrict__ qth, const __nv_bfloat16* __restrict__ qtl,
    float* __restrict__ qk) {
    extern __shared__ char smem[];
    if (blockIdx.y == 2)
        hmma_body<64, 1, 128>(wsh, wsl, qth, qtl, qk, blockIdx.x * 64, 0, blockIdx.z, smem);
    else
        hmma_body<256, 1, 256>(wvh, wvl, th, tl, vp, blockIdx.x * 64, blockIdx.y * 128,
                               blockIdx.z, smem);
}

// stand-alone pw GEMM (planar output)
__global__ __launch_bounds__(256, 3) void hmma_pw(
    const __nv_bfloat16* __restrict__ Wh, const __nv_bfloat16* __restrict__ Wl,
    const __nv_bfloat16* __restrict__ Xh, const __nv_bfloat16* __restrict__ Xl,
    float* __restrict__ Y) {
    extern __shared__ char smem[];
    hmma_body<256, 0, 256>(Wh, Wl, Xh, Xl, Y, blockIdx.x * 64, blockIdx.y * 128,
                           blockIdx.z, smem);
}

// ---------------- windowed attention v6 (unchanged) -----------------------------
#define AT_SV 0                       // [64][260] f32
#define AT_SQ (64 * 260)              // [64][68]
#define AT_SK (AT_SQ + 64 * 68)       // [64][68]
#define AT_SO AT_SQ                   // [64][133] (phase-2 overlay)
#define ATTN_SMEM ((64 * 260 + 2 * 64 * 68) * 4)  // 101376 B

__global__ __launch_bounds__(256, 2) void attn_kernel(
    const float* __restrict__ qk_pc, const float* __restrict__ vp_pc,
    const float* __restrict__ biasT, float* __restrict__ out) {
    extern __shared__ float sm[];
    float* sV = sm + AT_SV;
    float* sQ = sm + AT_SQ;
    float* sK = sm + AT_SK;
    float* sO = sm + AT_SO;

    const int wi = blockIdx.x;
    const int b = wi >> 10;
    const int rem = wi & 1023;
    const int y0 = (rem >> 5) << 3;
    const int x0 = (rem & 31) << 3;
    const int tid = threadIdx.x;
    const size_t pixBase = (size_t)b * NPIX + (size_t)y0 * 256 + x0;

#pragma unroll
    for (int i = 0; i < 8; i++) {
        int idx = tid + i * 256;          // 2048 float4
        int t = idx >> 5, f = idx & 31;
        size_t pix = pixBase + ((t >> 3) << 8) + (t & 7);
        float4 vv = *(const float4*)(qk_pc + pix * 128 + f * 4);
        if (f < 16)
            *(float4*)(sQ + t * 68 + f * 4) = vv;
        else
            *(float4*)(sK + t * 68 + (f - 16) * 4) = vv;
    }
#pragma unroll
    for (int i = 0; i < 16; i++) {
        int idx = tid + i * 256;          // 4096 float4
        int t = idx >> 6, c4 = idx & 63;
        size_t pix = pixBase + ((t >> 3) << 8) + (t & 7);
        *(float4*)(sV + t * 260 + c4 * 4) = *(const float4*)(vp_pc + pix * 256 + c4 * 4);
    }
    __syncthreads();

    const int h = tid >> 5;
    const int lane = tid & 31;
    const int r0 = lane, r1 = lane + 32;
    const float* bT = biasT + h * 4096;

    unsigned long long qa[4], qb[4];
    {
        const float4 a0 = *(const float4*)(sQ + r0 * 68 + h * 8);
        const float4 a1 = *(const float4*)(sQ + r0 * 68 + h * 8 + 4);
        PACK2(qa[0], a0.x, a0.y);
        PACK2(qa[1], a0.z, a0.w);
        PACK2(qa[2], a1.x, a1.y);
        PACK2(qa[3], a1.z, a1.w);
        const float4 b0 = *(const float4*)(sQ + r1 * 68 + h * 8);
        const float4 b1 = *(const float4*)(sQ + r1 * 68 + h * 8 + 4);
        PACK2(qb[0], b0.x, b0.y);
        PACK2(qb[1], b0.z, b0.w);
        PACK2(qb[2], b1.x, b1.y);
        PACK2(qb[3], b1.z, b1.w);
    }

    unsigned long long accA[16], accB[16];
#pragma unroll
    for (int j = 0; j < 16; j++) { accA[j] = 0ull; accB[j] = 0ull; }
    float sumA = 0.f, sumB = 0.f;

#pragma unroll 4
    for (int m = 0; m < 64; m++) {
        const ulonglong2* kr = (const ulonglong2*)(sK + m * 68 + h * 8);
        ulonglong2 ka = kr[0], kb = kr[1];
        unsigned long long dA, dB;
        MUL2(dA, qa[0], ka.x);
        FMA2(dA, qa[1], ka.y);
        FMA2(dA, qa[2], kb.x);
        FMA2(dA, qa[3], kb.y);
        MUL2(dB, qb[0], ka.x);
        FMA2(dB, qb[1], ka.y);
        FMA2(dB, qb[2], kb.x);
        FMA2(dB, qb[3], kb.y);
        float alo, ahi, blo, bhi;
        UNPACK2(alo, ahi, dA);
        UNPACK2(blo, bhi, dB);
        const float pA = __expf(alo + ahi + bT[m * 64 + r0]);
        const float pB = __expf(blo + bhi + bT[m * 64 + r1]);
        sumA += pA;
        sumB += pB;
        unsigned long long pA2, pB2;
        PACK2(pA2, pA, pA);
        PACK2(pB2, pB, pB);
        const ulonglong2* vr = (const ulonglong2*)(sV + m * 260 + h * 32);
#pragma unroll
        for (int t = 0; t < 8; t++) {
            ulonglong2 vv = vr[t];  // one load, two rows' FMAs
            FMA2(accA[t * 2], pA2, vv.x);
            FMA2(accA[t * 2 + 1], pA2, vv.y);
            FMA2(accB[t * 2], pB2, vv.x);
            FMA2(accB[t * 2 + 1], pB2, vv.y);
        }
    }
    const float rinvA = 1.f / sumA;
    const float rinvB = 1.f / sumB;
    __syncthreads();  // all reads of sQ/sK/sV done; sO may overlay

#pragma unroll
    for (int pass = 0; pass < 2; pass++) {
        if ((h >> 2) == pass) {
            const int cb = (h & 3) * 32;
            float* dstA = sO + r0 * 133 + cb;
            float* dstB = sO + r1 * 133 + cb;
#pragma unroll
            for (int u = 0; u < 16; u++) {
                float lo, hi;
                UNPACK2(lo, hi, accA[u]);
                dstA[u * 2] = lo * rinvA;
                dstA[u * 2 + 1] = hi * rinvA;
                UNPACK2(lo, hi, accB[u]);
                dstB[u * 2] = lo * rinvB;
                dstB[u * 2 + 1] = hi * rinvB;
            }
        }
        __syncthreads();
#pragma unroll 4
        for (int i = 0; i < 32; i++) {
            int idx = tid + i * 256;  // 8192 floats
            int c = idx >> 6, t = idx & 63;
            size_t g = ((size_t)(b * 256 + pass * 128 + c) << 16) +
                       ((size_t)y0 * 256 + x0) + ((t >> 3) << 8) + (t & 7);
            out[g] = sO[t * 133 + c];
        }
        __syncthreads();
    }
}

// ---------------- depthwise 8x8 conv + BN v2 ------------------------------------
// 64x64 tile, thread computes 2 adjacent output rows x 8 cols: each input row's
// LDS reads + f32x2 packs serve BOTH rows (row reads & packs per output halved).
__global__ __launch_bounds__(256) void dw_fn(const float* __restrict__ A,
                                             const float* __restrict__ Wd,
                                             const float* __restrict__ gamma,
                                             const float* __restrict__ beta,
                                             const float* __restrict__ mean,
                                             const float* __restrict__ var,
                                             float* __restrict__ O) {
    __shared__ float s[71][73];
    __shared__ float sw[64];
    const int bc = blockIdx.z;
    const int c = bc & 255;
    const int x0 = blockIdx.x * 64;
    const int y0 = blockIdx.y * 64;
    const float* Ab = A + (size_t)bc * NPIX;
    float* Ob = O + (size_t)bc * NPIX;
    const int tid = threadIdx.x;

    if (tid < 64) sw[tid] = Wd[c * 64 + tid];
    // halo region: 71 rows x 71 cols (pad y0-3..y0+67, x0-3..x0+67)
    for (int idx = tid; idx < 71 * 71; idx += 256) {
        int ly = idx / 71, lx = idx % 71;
        int gy = y0 - 3 + ly, gx = x0 - 3 + lx;
        float val = 0.f;
        if (gy >= 0 && gy <= 256 && gx >= 0 && gx <= 256) {
            int yy = (gy == 256) ? 254 : gy;
            int xx = (gx == 256) ? 254 : gx;
            val = Ab[yy * 256 + xx];
        }
        s[ly][lx] = val;
    }
    __syncthreads();

    const float inv = gamma[c] * rsqrtf(var[c] + 1e-5f);
    const float add = beta[c] - mean[c] * inv;
    const int ty = tid >> 3;         // 0..31 -> output rows 2ty, 2ty+1
    const int txg = (tid & 7) << 3;  // 0..56

    unsigned long long accA[4], accB[4];
#pragma unroll
    for (int u = 0; u < 4; u++) { accA[u] = 0ull; accB[u] = 0ull; }
#pragma unroll
    for (int i = 0; i < 9; i++) {
        float r[15];
#pragma unroll
        for (int t = 0; t < 15; t++) r[t] = s[2 * ty + i][txg + t];
        unsigned long long pr[14];
#pragma unroll
        for (int t = 0; t < 14; t++) PACK2(pr[t], r[t], r[t + 1]);
        if (i < 8) {
#pragma unroll
            for (int j = 0; j < 8; j++) {
                const float w = sw[i * 8 + j];
                unsigned long long w2;
                PACK2(w2, w, w);
#pragma unroll
                for (int u = 0; u < 4; u++) FMA2(accA[u], w2, pr[j + 2 * u]);
            }
        }
        if (i >= 1) {
#pragma unroll
            for (int j = 0; j < 8; j++) {
                const float w = sw[(i - 1) * 8 + j];
                unsigned long long w2;
                PACK2(w2, w, w);
#pragma unroll
                for (int u = 0; u < 4; u++) FMA2(accB[u], w2, pr[j + 2 * u]);
            }
        }
    }
    const int baseA = (y0 + 2 * ty) * 256 + x0 + txg;
#pragma unroll
    for (int u = 0; u < 4; u++) {
        float lo, hi;
        UNPACK2(lo, hi, accA[u]);
        Ob[baseA + 2 * u] = lo * inv + add;
        Ob[baseA + 2 * u + 1] = hi * inv + add;
        UNPACK2(lo, hi, accB[u]);
        Ob[baseA + 256 + 2 * u] = lo * inv + add;
        Ob[baseA + 256 + 2 * u + 1] = hi * inv + add;
    }
}

// ---------------- launch --------------------------------------------------------
extern "C" void kernel_launch(void* const* d_in, const int* in_sizes, int n_in,
                              void* d_out, int out_size) {
    const float* q = (const float*)d_in[0];
    const float* v = (const float*)d_in[1];
    const float* Wq = (const float*)d_in[2];
    const float* Wk = (const float*)d_in[3];
    const float* Wv = (const float*)d_in[4];
    const float* bias_table = (const float*)d_in[5];
    const float* dwk = (const float*)d_in[6];
    const float* gamma = (const float*)d_in[7];
    const float* beta = (const float*)d_in[8];
    const float* mean = (const float*)d_in[9];
    const float* var = (const float*)d_in[10];
    const float* pw = (const float*)d_in[11];
    const int* rel = (const int*)d_in[12];
    float* out = (float*)d_out;

    float *vp, *qk, *attn, *dw, *biasT;
    __nv_bfloat16 *th, *tl, *qth, *qtl, *wsh, *wsl, *wvh, *wvl, *pwh, *pwl;
    cudaGetSymbolAddress((void**)&vp, g_vp);
    cudaGetSymbolAddress((void**)&qk, g_qk);
    cudaGetSymbolAddress((void**)&attn, g_attn);
    cudaGetSymbolAddress((void**)&dw, g_dw);
    cudaGetSymbolAddress((void**)&biasT, g_biasT);
    cudaGetSymbolAddress((void**)&th, g_Th);
    cudaGetSymbolAddress((void**)&tl, g_Tl);
    cudaGetSymbolAddress((void**)&qth, g_qTh);
    cudaGetSymbolAddress((void**)&qtl, g_qTl);
    cudaGetSymbolAddress((void**)&wsh, g_Wsh);
    cudaGetSymbolAddress((void**)&wsl, g_Wsl);
    cudaGetSymbolAddress((void**)&wvh, g_Wvh);
    cudaGetSymbolAddress((void**)&wvl, g_Wvl);
    cudaGetSymbolAddress((void**)&pwh, g_pwh);
    cudaGetSymbolAddress((void**)&pwl, g_pwl);

    cudaFuncSetAttribute(attn_kernel, cudaFuncAttributeMaxDynamicSharedMemorySize, ATTN_SMEM);
    cudaFuncSetAttribute(gemm_all, cudaFuncAttributeMaxDynamicSharedMemorySize, HM_SMEM);
    cudaFuncSetAttribute(hmma_pw, cudaFuncAttributeMaxDynamicSharedMemorySize, HM_SMEM);

    // 0) merged transposes + prep: y==0 q, y 1..4 v, y==5 prep (z==0)
    convT_all<<<dim3(1024, 6, 2), 256>>>(q, v, qth, qtl, th, tl,
                                         Wk, Wq, bias_table, rel, Wv, pw,
                                         wsh, wsl, biasT, wvh, wvl, pwh, pwl);
    // 1) merged GEMMs: y<2 -> vp (token-major), y==2 -> qk (token-major)
    gemm_all<<<dim3(1024, 3, 2), 256, HM_SMEM>>>(wvh, wvl, th, tl, vp,
                                                 wsh, wsl, qth, qtl, qk);
    // 2) windowed attention v6 -> planar
    attn_kernel<<<2048, 256, ATTN_SMEM>>>(qk, vp, biasT, attn);
    // 3) depthwise 8x8 + BN v2 (2 rows/thread)   (launch index 3: ncu samples this)
    dw_fn<<<dim3(4, 4, 512), 256>>>(attn, dwk, gamma, beta, mean, var, dw);
    // 4-5) pointwise projection -> output (planar)
    convT256<<<dim3(1024, 4, 2), 256>>>(dw, th, tl);
    hmma_pw<<<dim3(1024, 2, 2), 256, HM_SMEM>>>(pwh, pwl, th, tl, out);
}

// round 17
// speedup vs baseline: 1.0763x; 1.0763x over previous
#include <cuda_runtime.h>
#include <cuda_bf16.h>
#include <cstdint>
#include <math.h>

#define NPIX 65536  // 256*256

// ---------------- scratch (device globals; no allocation allowed) -------------
__device__ float g_vp[33554432];   // vp_pc: [b][p][256] f32 (token-major)
__device__ float g_qk[16777216];   // qk_pc: [b][p][128] f32 (qp | kp)
__device__ float g_attn[33554432]; // planar [b][c][p]
__device__ float g_dw[33554432];   // planar
__device__ float g_biasT[32768];   // [h][m][r]
__device__ __nv_bfloat16 g_Th[33554432];  // transposed hi  [b][p][c]  (v / dw)
__device__ __nv_bfloat16 g_Tl[33554432];  // transposed lo
__device__ __nv_bfloat16 g_qTh[8388608], g_qTl[8388608];  // q transposed [b][p][64]
__device__ __nv_bfloat16 g_Wsh[8192], g_Wsl[8192];        // [Wq*s;Wkq] 128x64
__device__ __nv_bfloat16 g_Wvh[65536], g_Wvl[65536];
__device__ __nv_bfloat16 g_pwh[65536], g_pwl[65536];

// ================= helpers ======================================================
__device__ __forceinline__ uint32_t smem_u32(const void* p) {
    uint32_t a;
    asm("{ .reg .u64 t; cvta.to.shared.u64 t, %1; cvt.u32.u64 %0, t; }" : "=r"(a) : "l"(p));
    return a;
}
__device__ __forceinline__ void ldsm4(uint32_t* r, uint32_t addr) {
    asm volatile("ldmatrix.sync.aligned.m8n8.x4.shared.b16 {%0,%1,%2,%3}, [%4];"
                 : "=r"(r[0]), "=r"(r[1]), "=r"(r[2]), "=r"(r[3]) : "r"(addr));
}
__device__ __forceinline__ void mma16816(float* c, const uint32_t* a, const uint32_t* b) {
    asm volatile(
        "mma.sync.aligned.m16n8k16.row.col.f32.bf16.bf16.f32 "
        "{%0,%1,%2,%3}, {%4,%5,%6,%7}, {%8,%9}, {%0,%1,%2,%3};"
        : "+f"(c[0]), "+f"(c[1]), "+f"(c[2]), "+f"(c[3])
        : "r"(a[0]), "r"(a[1]), "r"(a[2]), "r"(a[3]), "r"(b[0]), "r"(b[1]));
}
__device__ __forceinline__ void cp16(uint32_t saddr, const void* g) {
    asm volatile("cp.async.cg.shared.global [%0], [%1], 16;" ::"r"(saddr), "l"(g));
}
#define CP_COMMIT() asm volatile("cp.async.commit_group;" ::: "memory")
#define CP_WAIT0() asm volatile("cp.async.wait_group 0;" ::: "memory")
#define FMA2(d, a, b) asm("fma.rn.f32x2 %0, %1, %2, %0;" : "+l"(d) : "l"(a), "l"(b))
#define MUL2(d, a, b) asm("mul.rn.f32x2 %0, %1, %2;" : "=l"(d) : "l"(a), "l"(b))
#define PACK2(d, lo, hi) asm("mov.b64 %0, {%1, %2};" : "=l"(d) : "f"(lo), "f"(hi))
#define UNPACK2(lo, hi, d) asm("mov.b64 {%0, %1}, %2;" : "=f"(lo), "=f"(hi) : "l"(d))

// ---------------- transpose + hi/lo convert body --------------------------------
template <int CDIM>
__device__ __forceinline__ void convT_body(const float* __restrict__ X,
                                           __nv_bfloat16* __restrict__ Th,
                                           __nv_bfloat16* __restrict__ Tl,
                                           int p0, int c0, int b) {
    __shared__ float s[64][65];
    const int tid = threadIdx.x;
    const float* Xb = X + ((size_t)b * CDIM + c0) * NPIX + p0;
#pragma unroll
    for (int i = 0; i < 16; i++) {
        int idx = tid + i * 256;
        int c = idx >> 6, p = idx & 63;
        s[c][p] = Xb[(size_t)c * NPIX + p];
    }
    __syncthreads();
    const size_t ob = ((size_t)b * NPIX + p0) * CDIM + c0;
#pragma unroll
    for (int i = 0; i < 16; i++) {
        int idx = tid + i * 256;
        int p = idx >> 6, c = idx & 63;
        float x = s[c][p];
        __nv_bfloat16 h = __float2bfloat16(x);
        Th[ob + (size_t)p * CDIM + c] = h;
        Tl[ob + (size_t)p * CDIM + c] = __float2bfloat16(x - __bfloat162float(h));
    }
}

// merged: y==0 -> q transpose, y in 1..4 -> v transpose, y==5 -> prep (z==0 only)
__global__ __launch_bounds__(256) void convT_all(
    const float* __restrict__ q, const float* __restrict__ v,
    __nv_bfloat16* __restrict__ qth, __nv_bfloat16* __restrict__ qtl,
    __nv_bfloat16* __restrict__ th, __nv_bfloat16* __restrict__ tl,
    const float* __restrict__ Wk, const float* __restrict__ Wq,
    const float* __restrict__ bias_table, const int* __restrict__ rel,
    const float* __restrict__ Wv, const float* __restrict__ pw,
    __nv_bfloat16* __restrict__ Wsh, __nv_bfloat16* __restrict__ Wsl,
    float* __restrict__ biasT,
    __nv_bfloat16* __restrict__ Wvh, __nv_bfloat16* __restrict__ Wvl,
    __nv_bfloat16* __restrict__ pwh, __nv_bfloat16* __restrict__ pwl) {
    if (blockIdx.y == 0) {
        convT_body<64>(q, qth, qtl, blockIdx.x * 64, 0, blockIdx.z);
    } else if (blockIdx.y <= 4) {
        convT_body<256>(v, th, tl, blockIdx.x * 64, (blockIdx.y - 1) * 64, blockIdx.z);
    } else {
        if (blockIdx.z != 0) return;
        const int bx = blockIdx.x;
        if (bx == 0) {
            __shared__ float swkq[4096];
            const float scale = 0.35355339059327373f;
            for (int idx = threadIdx.x; idx < 4096; idx += 256) {
                int o = idx >> 6, c = idx & 63;
                float s = 0.f;
#pragma unroll 8
                for (int j = 0; j < 64; j++) s += Wk[o * 64 + j] * Wq[j * 64 + c];
                swkq[idx] = s;
                float a = Wq[idx] * scale;
                __nv_bfloat16 h = __float2bfloat16(a);
                Wsh[idx] = h;
                Wsl[idx] = __float2bfloat16(a - __bfloat162float(h));
            }
            __syncthreads();
            for (int idx = threadIdx.x; idx < 4096; idx += 256) {
                float a = swkq[idx];
                __nv_bfloat16 h = __float2bfloat16(a);
                Wsh[4096 + idx] = h;
                Wsl[4096 + idx] = __float2bfloat16(a - __bfloat162float(h));
            }
        } else if (bx <= 128) {
            int idx = (bx - 1) * 256 + threadIdx.x;  // 32768
            int h = idx >> 12, rm = idx & 4095, m = rm >> 6, r = rm & 63;
            biasT[idx] = bias_table[rel[r * 64 + m] * 8 + h];
        } else if (bx <= 384) {
            int idx = (bx - 129) * 256 + threadIdx.x;  // 65536
            float a = Wv[idx];
            __nv_bfloat16 ah = __float2bfloat16(a);
            Wvh[idx] = ah;
            Wvl[idx] = __float2bfloat16(a - __bfloat162float(ah));
            float b = pw[idx];
            __nv_bfloat16 bh = __float2bfloat16(b);
            pwh[idx] = bh;
            pwl[idx] = __float2bfloat16(b - __bfloat162float(bh));
        }
    }
}

// stand-alone for the dw -> pw transpose
__global__ __launch_bounds__(256) void convT256(const float* __restrict__ X,
                                                __nv_bfloat16* __restrict__ Th,
                                                __nv_bfloat16* __restrict__ Tl) {
    convT_body<256>(X, Th, Tl, blockIdx.x * 64, blockIdx.y * 64, blockIdx.z);
}

// ================= HMMA bf16x3 GEMM body (128o x 64p, 3 CTA/SM) =================
#define RS 72
#define SA_H 0
#define SA_L (128 * RS * 2)
#define SB_H (2 * 128 * RS * 2)
#define SB_L (2 * 128 * RS * 2 + 64 * RS * 2)
#define HM_SMEM (2 * 128 * RS * 2 + 2 * 64 * RS * 2)  // 55296 B

template <int CIN, int PCOUT, int CD>
__device__ __forceinline__ void hmma_body(
    const __nv_bfloat16* __restrict__ Wh, const __nv_bfloat16* __restrict__ Wl,
    const __nv_bfloat16* __restrict__ Xh, const __nv_bfloat16* __restrict__ Xl,
    float* __restrict__ Y, int pBase, int oBase, int b, char* smem) {
    const uint32_t sb = smem_u32(smem);
    const int tid = threadIdx.x;
    const int wid = tid >> 5, lane = tid & 31;
    const int wm = wid & 3, wn = wid >> 2;
    const size_t xrow = (size_t)b * NPIX + pBase;
    const int NKC = CIN / 64;

    float acc[2][4][4];
#pragma unroll
    for (int i = 0; i < 2; i++)
#pragma unroll
        for (int j = 0; j < 4; j++)
#pragma unroll
            for (int k = 0; k < 4; k++) acc[i][j][k] = 0.f;

    const int lrow = lane & 15;
    const int lkoff = (lane >> 4) * 8;
    const int arow = tid >> 3, ac8 = tid & 7;

    for (int kc = 0; kc < NKC; kc++) {
        const size_t kb = (size_t)kc * 64;
#pragma unroll
        for (int i = 0; i < 4; i++) {
            int row = arow + i * 32;
            size_t g = (size_t)(oBase + row) * CIN + kb + ac8 * 8;
            uint32_t so = row * (RS * 2) + ac8 * 16;
            cp16(sb + SA_H + so, Wh + g);
            cp16(sb + SA_L + so, Wl + g);
        }
#pragma unroll
        for (int i = 0; i < 2; i++) {
            int row = arow + i * 32;
            size_t g = (xrow + row) * CIN + kb + ac8 * 8;
            uint32_t so = row * (RS * 2) + ac8 * 16;
            cp16(sb + SB_H + so, Xh + g);
            cp16(sb + SB_L + so, Xl + g);
        }
        CP_COMMIT();
        CP_WAIT0();
        __syncthreads();

#pragma unroll
        for (int ks = 0; ks < 4; ks++) {
            const int kbo = ks * 16 + lkoff;
            uint32_t ah[2][4], al[2][4];
#pragma unroll
            for (int mt = 0; mt < 2; mt++) {
                uint32_t ro = (wm * 32 + mt * 16 + lrow) * (RS * 2) + kbo * 2;
                ldsm4(ah[mt], sb + SA_H + ro);
                ldsm4(al[mt], sb + SA_L + ro);
            }
            uint32_t bh[2][4], bl[2][4];
#pragma unroll
            for (int nt = 0; nt < 2; nt++) {
                uint32_t ro = (wn * 32 + nt * 16 + lrow) * (RS * 2) + kbo * 2;
                ldsm4(bh[nt], sb + SB_H + ro);
                ldsm4(bl[nt], sb + SB_L + ro);
            }
#pragma unroll
            for (int mt = 0; mt < 2; mt++) {
#pragma unroll
                for (int n8 = 0; n8 < 4; n8++) {
                    const int nt = n8 >> 1, half = n8 & 1;
                    uint32_t bfh[2] = {bh[nt][half], bh[nt][half + 2]};
                    uint32_t bfl[2] = {bl[nt][half], bl[nt][half + 2]};
                    mma16816(acc[mt][n8], ah[mt], bfh);
                    mma16816(acc[mt][n8], ah[mt], bfl);
                    mma16816(acc[mt][n8], al[mt], bfh);
                }
            }
        }
        __syncthreads();
    }

    if constexpr (PCOUT) {
        float* sO = (float*)smem;
#pragma unroll
        for (int mt = 0; mt < 2; mt++) {
#pragma unroll
            for (int n8 = 0; n8 < 4; n8++) {
                int ml = wm * 32 + mt * 16 + (lane >> 2);
                int pl = wn * 32 + n8 * 8 + (lane & 3) * 2;
                sO[pl * 132 + ml] = acc[mt][n8][0];
                sO[(pl + 1) * 132 + ml] = acc[mt][n8][1];
                sO[pl * 132 + ml + 8] = acc[mt][n8][2];
                sO[(pl + 1) * 132 + ml + 8] = acc[mt][n8][3];
            }
        }
        __syncthreads();
#pragma unroll
        for (int i = 0; i < 8; i++) {
            int idx = tid + i * 256;  // 2048 float4
            int p = idx >> 5, o4 = (idx & 31) * 4;
            *(float4*)(Y + (xrow + p) * CD + oBase + o4) = *(const float4*)(sO + p * 132 + o4);
        }
    } else {
        const int mrow = oBase + wm * 32 + (lane >> 2);
        const int pcol = pBase + wn * 32 + (lane & 3) * 2;
#pragma unroll
        for (int mt = 0; mt < 2; mt++) {
#pragma unroll
            for (int n8 = 0; n8 < 4; n8++) {
                size_t base = ((size_t)(b * 256 + mrow + mt * 16)) * NPIX + pcol + n8 * 8;
                *(float2*)(Y + base) = make_float2(acc[mt][n8][0], acc[mt][n8][1]);
                *(float2*)(Y + base + 8ull * NPIX) = make_float2(acc[mt][n8][2], acc[mt][n8][3]);
            }
        }
    }
}

// merged vp + qk GEMM: y<2 -> vp tile TOKEN-MAJOR (oBase=y*128), y==2 -> qk
__global__ __launch_bounds__(256, 3) void gemm_all(
    const __nv_bfloat16* __restrict__ wvh, const __nv_bfloat16* __restrict__ wvl,
    const __nv_bfloat16* __restrict__ th, const __nv_bfloat16* __restrict__ tl,
    float* __restrict__ vp,
    const __nv_bfloat16* __restrict__ wsh, const __nv_bfloat16* __restrict__ wsl,
    const __nv_bfloat16* __restrict__ qth, const __nv_bfloat16* __restrict__ qtl,
    float* __restrict__ qk) {
    extern __shared__ char smem[];
    if (blockIdx.y == 2)
        hmma_body<64, 1, 128>(wsh, wsl, qth, qtl, qk, blockIdx.x * 64, 0, blockIdx.z, smem);
    else
        hmma_body<256, 1, 256>(wvh, wvl, th, tl, vp, blockIdx.x * 64, blockIdx.y * 128,
                               blockIdx.z, smem);
}

// stand-alone pw GEMM (planar output)
__global__ __launch_bounds__(256, 3) void hmma_pw(
    const __nv_bfloat16* __restrict__ Wh, const __nv_bfloat16* __restrict__ Wl,
    const __nv_bfloat16* __restrict__ Xh, const __nv_bfloat16* __restrict__ Xl,
    float* __restrict__ Y) {
    extern __shared__ char smem[];
    hmma_body<256, 0, 256>(Wh, Wl, Xh, Xl, Y, blockIdx.x * 64, blockIdx.y * 128,
                           blockIdx.z, smem);
}

// ---------------- windowed attention v6 (unchanged) -----------------------------
#define AT_SV 0                       // [64][260] f32
#define AT_SQ (64 * 260)              // [64][68]
#define AT_SK (AT_SQ + 64 * 68)       // [64][68]
#define AT_SO AT_SQ                   // [64][133] (phase-2 overlay)
#define ATTN_SMEM ((64 * 260 + 2 * 64 * 68) * 4)  // 101376 B

__global__ __launch_bounds__(256, 2) void attn_kernel(
    const float* __restrict__ qk_pc, const float* __restrict__ vp_pc,
    const float* __restrict__ biasT, float* __restrict__ out) {
    extern __shared__ float sm[];
    float* sV = sm + AT_SV;
    float* sQ = sm + AT_SQ;
    float* sK = sm + AT_SK;
    float* sO = sm + AT_SO;

    const int wi = blockIdx.x;
    const int b = wi >> 10;
    const int rem = wi & 1023;
    const int y0 = (rem >> 5) << 3;
    const int x0 = (rem & 31) << 3;
    const int tid = threadIdx.x;
    const size_t pixBase = (size_t)b * NPIX + (size_t)y0 * 256 + x0;

#pragma unroll
    for (int i = 0; i < 8; i++) {
        int idx = tid + i * 256;          // 2048 float4
        int t = idx >> 5, f = idx & 31;
        size_t pix = pixBase + ((t >> 3) << 8) + (t & 7);
        float4 vv = *(const float4*)(qk_pc + pix * 128 + f * 4);
        if (f < 16)
            *(float4*)(sQ + t * 68 + f * 4) = vv;
        else
            *(float4*)(sK + t * 68 + (f - 16) * 4) = vv;
    }
#pragma unroll
    for (int i = 0; i < 16; i++) {
        int idx = tid + i * 256;          // 4096 float4
        int t = idx >> 6, c4 = idx & 63;
        size_t pix = pixBase + ((t >> 3) << 8) + (t & 7);
        *(float4*)(sV + t * 260 + c4 * 4) = *(const float4*)(vp_pc + pix * 256 + c4 * 4);
    }
    __syncthreads();

    const int h = tid >> 5;
    const int lane = tid & 31;
    const int r0 = lane, r1 = lane + 32;
    const float* bT = biasT + h * 4096;

    unsigned long long qa[4], qb[4];
    {
        const float4 a0 = *(const float4*)(sQ + r0 * 68 + h * 8);
        const float4 a1 = *(const float4*)(sQ + r0 * 68 + h * 8 + 4);
        PACK2(qa[0], a0.x, a0.y);
        PACK2(qa[1], a0.z, a0.w);
        PACK2(qa[2], a1.x, a1.y);
        PACK2(qa[3], a1.z, a1.w);
        const float4 b0 = *(const float4*)(sQ + r1 * 68 + h * 8);
        const float4 b1 = *(const float4*)(sQ + r1 * 68 + h * 8 + 4);
        PACK2(qb[0], b0.x, b0.y);
        PACK2(qb[1], b0.z, b0.w);
        PACK2(qb[2], b1.x, b1.y);
        PACK2(qb[3], b1.z, b1.w);
    }

    unsigned long long accA[16], accB[16];
#pragma unroll
    for (int j = 0; j < 16; j++) { accA[j] = 0ull; accB[j] = 0ull; }
    float sumA = 0.f, sumB = 0.f;

#pragma unroll 4
    for (int m = 0; m < 64; m++) {
        const ulonglong2* kr = (const ulonglong2*)(sK + m * 68 + h * 8);
        ulonglong2 ka = kr[0], kb = kr[1];
        unsigned long long dA, dB;
        MUL2(dA, qa[0], ka.x);
        FMA2(dA, qa[1], ka.y);
        FMA2(dA, qa[2], kb.x);
        FMA2(dA, qa[3], kb.y);
        MUL2(dB, qb[0], ka.x);
        FMA2(dB, qb[1], ka.y);
        FMA2(dB, qb[2], kb.x);
        FMA2(dB, qb[3], kb.y);
        float alo, ahi, blo, bhi;
        UNPACK2(alo, ahi, dA);
        UNPACK2(blo, bhi, dB);
        const float pA = __expf(alo + ahi + bT[m * 64 + r0]);
        const float pB = __expf(blo + bhi + bT[m * 64 + r1]);
        sumA += pA;
        sumB += pB;
        unsigned long long pA2, pB2;
        PACK2(pA2, pA, pA);
        PACK2(pB2, pB, pB);
        const ulonglong2* vr = (const ulonglong2*)(sV + m * 260 + h * 32);
#pragma unroll
        for (int t = 0; t < 8; t++) {
            ulonglong2 vv = vr[t];  // one load, two rows' FMAs
            FMA2(accA[t * 2], pA2, vv.x);
            FMA2(accA[t * 2 + 1], pA2, vv.y);
            FMA2(accB[t * 2], pB2, vv.x);
            FMA2(accB[t * 2 + 1], pB2, vv.y);
        }
    }
    const float rinvA = 1.f / sumA;
    const float rinvB = 1.f / sumB;
    __syncthreads();  // all reads of sQ/sK/sV done; sO may overlay

#pragma unroll
    for (int pass = 0; pass < 2; pass++) {
        if ((h >> 2) == pass) {
            const int cb = (h & 3) * 32;
            float* dstA = sO + r0 * 133 + cb;
            float* dstB = sO + r1 * 133 + cb;
#pragma unroll
            for (int u = 0; u < 16; u++) {
                float lo, hi;
                UNPACK2(lo, hi, accA[u]);
                dstA[u * 2] = lo * rinvA;
                dstA[u * 2 + 1] = hi * rinvA;
                UNPACK2(lo, hi, accB[u]);
                dstB[u * 2] = lo * rinvB;
                dstB[u * 2 + 1] = hi * rinvB;
            }
        }
        __syncthreads();
#pragma unroll 4
        for (int i = 0; i < 32; i++) {
            int idx = tid + i * 256;  // 8192 floats
            int c = idx >> 6, t = idx & 63;
            size_t g = ((size_t)(b * 256 + pass * 128 + c) << 16) +
                       ((size_t)y0 * 256 + x0) + ((t >> 3) << 8) + (t & 7);
            out[g] = sO[t * 133 + c];
        }
        __syncthreads();
    }
}

// ---------------- depthwise 8x8 conv + BN v3 ------------------------------------
// R15 structure (64x32 tile, 1 row x 8 cols per thread) but row reads as ALIGNED
// LDS.64 pairs: pe[t]={r2t,r2t+1} load directly into register pairs (no pack);
// only 7 odd pairs po[t]={r2t+1,r2t+2} are built. 15 LDS + 14 packs -> 8 LDS + 7.
__global__ __launch_bounds__(256) void dw_fn(const float* __restrict__ A,
                                             const float* __restrict__ Wd,
                                             const float* __restrict__ gamma,
                                             const float* __restrict__ beta,
                                             const float* __restrict__ mean,
                                             const float* __restrict__ var,
                                             float* __restrict__ O) {
    __shared__ float s[39][74];  // row stride 296 B (8B multiple for LDS.64)
    __shared__ float sw[64];
    const int bc = blockIdx.z;
    const int c = bc & 255;
    const int x0 = blockIdx.x * 64;
    const int y0 = blockIdx.y * 32;
    const float* Ab = A + (size_t)bc * NPIX;
    float* Ob = O + (size_t)bc * NPIX;
    const int tid = threadIdx.x;

    if (tid < 64) sw[tid] = Wd[c * 64 + tid];
    for (int idx = tid; idx < 39 * 72; idx += 256) {
        int ly = idx / 72, lx = idx % 72;  // cols 0..71 (71 halo + 1 pad col)
        int gy = y0 - 3 + ly, gx = x0 - 3 + lx;
        float val = 0.f;
        if (gy >= 0 && gy <= 256 && gx >= 0 && gx <= 256) {
            int yy = (gy == 256) ? 254 : gy;
            int xx = (gx == 256) ? 254 : gx;
            val = Ab[yy * 256 + xx];
        }
        s[ly][lx] = val;
    }
    __syncthreads();

    const float inv = gamma[c] * rsqrtf(var[c] + 1e-5f);
    const float add = beta[c] - mean[c] * inv;
    const int ty = tid >> 3;
    const int txg = (tid & 7) << 3;

    unsigned long long acc2[4];
#pragma unroll
    for (int u = 0; u < 4; u++) acc2[u] = 0ull;
#pragma unroll
    for (int i = 0; i < 8; i++) {
        // aligned pair loads: pe[t] = {r[2t], r[2t+1]}
        const unsigned long long* rowp = (const unsigned long long*)(&s[ty + i][txg]);
        unsigned long long pe[8];
#pragma unroll
        for (int t = 0; t < 8; t++) pe[t] = rowp[t];
        // odd pairs po[t] = {r[2t+1], r[2t+2]}
        unsigned long long po[7];
#pragma unroll
        for (int t = 0; t < 7; t++) {
            float e0, e1, n0, n1;
            UNPACK2(e0, e1, pe[t]);
            UNPACK2(n0, n1, pe[t + 1]);
            PACK2(po[t], e1, n0);
        }
#pragma unroll
        for (int j2 = 0; j2 < 4; j2++) {
            const float we = sw[i * 8 + 2 * j2];
            unsigned long long w2e;
            PACK2(w2e, we, we);
#pragma unroll
            for (int u = 0; u < 4; u++) FMA2(acc2[u], w2e, pe[j2 + u]);
            const float wo = sw[i * 8 + 2 * j2 + 1];
            unsigned long long w2o;
            PACK2(w2o, wo, wo);
#pragma unroll
            for (int u = 0; u < 4; u++) FMA2(acc2[u], w2o, po[j2 + u]);
        }
    }
    const int base = (y0 + ty) * 256 + x0 + txg;
#pragma unroll
    for (int u = 0; u < 4; u++) {
        float lo, hi;
        UNPACK2(lo, hi, acc2[u]);
        Ob[base + 2 * u] = lo * inv + add;
        Ob[base + 2 * u + 1] = hi * inv + add;
    }
}

// ---------------- launch --------------------------------------------------------
extern "C" void kernel_launch(void* const* d_in, const int* in_sizes, int n_in,
                              void* d_out, int out_size) {
    const float* q = (const float*)d_in[0];
    const float* v = (const float*)d_in[1];
    const float* Wq = (const float*)d_in[2];
    const float* Wk = (const float*)d_in[3];
    const float* Wv = (const float*)d_in[4];
    const float* bias_table = (const float*)d_in[5];
    const float* dwk = (const float*)d_in[6];
    const float* gamma = (const float*)d_in[7];
    const float* beta = (const float*)d_in[8];
    const float* mean = (const float*)d_in[9];
    const float* var = (const float*)d_in[10];
    const float* pw = (const float*)d_in[11];
    const int* rel = (const int*)d_in[12];
    float* out = (float*)d_out;

    float *vp, *qk, *attn, *dw, *biasT;
    __nv_bfloat16 *th, *tl, *qth, *qtl, *wsh, *wsl, *wvh, *wvl, *pwh, *pwl;
    cudaGetSymbolAddress((void**)&vp, g_vp);
    cudaGetSymbolAddress((void**)&qk, g_qk);
    cudaGetSymbolAddress((void**)&attn, g_attn);
    cudaGetSymbolAddress((void**)&dw, g_dw);
    cudaGetSymbolAddress((void**)&biasT, g_biasT);
    cudaGetSymbolAddress((void**)&th, g_Th);
    cudaGetSymbolAddress((void**)&tl, g_Tl);
    cudaGetSymbolAddress((void**)&qth, g_qTh);
    cudaGetSymbolAddress((void**)&qtl, g_qTl);
    cudaGetSymbolAddress((void**)&wsh, g_Wsh);
    cudaGetSymbolAddress((void**)&wsl, g_Wsl);
    cudaGetSymbolAddress((void**)&wvh, g_Wvh);
    cudaGetSymbolAddress((void**)&wvl, g_Wvl);
    cudaGetSymbolAddress((void**)&pwh, g_pwh);
    cudaGetSymbolAddress((void**)&pwl, g_pwl);

    cudaFuncSetAttribute(attn_kernel, cudaFuncAttributeMaxDynamicSharedMemorySize, ATTN_SMEM);
    cudaFuncSetAttribute(gemm_all, cudaFuncAttributeMaxDynamicSharedMemorySize, HM_SMEM);
    cudaFuncSetAttribute(hmma_pw, cudaFuncAttributeMaxDynamicSharedMemorySize, HM_SMEM);

    // 0) merged transposes + prep: y==0 q, y 1..4 v, y==5 prep (z==0)
    convT_all<<<dim3(1024, 6, 2), 256>>>(q, v, qth, qtl, th, tl,
                                         Wk, Wq, bias_table, rel, Wv, pw,
                                         wsh, wsl, biasT, wvh, wvl, pwh, pwl);
    // 1) merged GEMMs: y<2 -> vp (token-major), y==2 -> qk (token-major)
    gemm_all<<<dim3(1024, 3, 2), 256, HM_SMEM>>>(wvh, wvl, th, tl, vp,
                                                 wsh, wsl, qth, qtl, qk);
    // 2) windowed attention v6 -> planar
    attn_kernel<<<2048, 256, ATTN_SMEM>>>(qk, vp, biasT, attn);
    // 3) depthwise 8x8 + BN v3 (aligned-pair LDS.64)  (launch index 3: profiled)
    dw_fn<<<dim3(4, 8, 512), 256>>>(attn, dwk, gamma, beta, mean, var, dw);
    // 4-5) pointwise projection -> output (planar)
    convT256<<<dim3(1024, 4, 2), 256>>>(dw, th, tl);
    hmma_pw<<<dim3(1024, 2, 2), 256, HM_SMEM>>>(pwh, pwl, th, tl, out);
}